// round 10
// baseline (speedup 1.0000x reference)
#include <cuda_runtime.h>
#include <stdint.h>

#define HH 512
#define WW 512
#define HW (HH*WW)
#define NS 8            // samples
#define NIMG 16         // samples * {pred, mask}
#define KP 1024         // points per set
#define T_MST 256
#define NPT 4           // nodes per MST thread
#define UMAXV 0xFFFFFFFFu
#define SENTX 46000u    // retired-node x (scaled); cands land in [8.79e8, 2.39e9]
#define SKIPTHR 0x20000000u  // 2^29: real keys <= 5.348e8 < 2^29; sentinel cands above
#define WPR 16          // 512/32 words per row

// ---------------- scratch (static device globals; no allocation) ----------------
__device__ unsigned g_mask[NIMG * 8192];          // binarized bitmasks (512x512 bits)
__device__ unsigned g_fbits[NIMG * 8192];         // lbp<THR flag bitmasks
__device__ float2   g_pts[NIMG][KP];              // selected points (r, c) float
__device__ unsigned g_pti[NIMG][KP];              // packed int coords (r<<16)|c
__device__ int2     g_edges[NIMG][KP - 1];        // MST edges (src, j)
__device__ float    g_part[NIMG];                 // per-(sample,tree) partial norms

// ---------------- 1) binarize -> bitmasks ---------------------------------------
__global__ void binarize_kernel(const float* __restrict__ mo, const float* __restrict__ lb) {
    int gid = blockIdx.x * blockDim.x + threadIdx.x;   // exactly NS*HW threads
    int s = gid >> 18;
    int p = gid & (HW - 1);
    unsigned bp = __ballot_sync(0xffffffffu, __ldg(mo + gid) > 0.0f);  // sigmoid>0.5 <=> x>0
    unsigned bm = __ballot_sync(0xffffffffu, __ldg(lb + gid) > 0.5f);
    if ((threadIdx.x & 31) == 0) {
        int w = p >> 5;
        g_mask[(2 * s)     * 8192 + w] = bp;
        g_mask[(2 * s + 1) * 8192 + w] = bm;
    }
}

// ---------------- 2) uniform LBP on bitmasks (exact) ----------------------------
__device__ __forceinline__ unsigned maj3(unsigned a, unsigned b, unsigned c) {
    return (a & b) | (c & (a ^ b));
}
__device__ __forceinline__ void sum8(const unsigned b[8],
                                     unsigned& s0, unsigned& s1, unsigned& s2, unsigned& s3) {
    unsigned t0 = b[0] ^ b[1], c0 = b[0] & b[1];
    unsigned t1 = b[2] ^ b[3], c1 = b[2] & b[3];
    unsigned t2 = b[4] ^ b[5], c2 = b[4] & b[5];
    unsigned t3 = b[6] ^ b[7], c3 = b[6] & b[7];
    unsigned u0 = t0 ^ t1, d0 = t0 & t1;
    unsigned u1 = t2 ^ t3, d1 = t2 & t3;
    s0 = u0 ^ u1;
    unsigned e0 = u0 & u1;
    unsigned p0 = c0 ^ c1 ^ c2, q0 = maj3(c0, c1, c2);
    unsigned p1 = c3 ^ d0 ^ d1, q1 = maj3(c3, d0, d1);
    s1 = p0 ^ p1 ^ e0;
    unsigned q2 = maj3(p0, p1, e0);
    s2 = q0 ^ q1 ^ q2;
    s3 = maj3(q0, q1, q2);
}

struct RowBits { unsigned C, Lc, Rc, QL, QR; };

__device__ __forceinline__ RowBits rowbits(const unsigned* __restrict__ M, int y, int w) {
    RowBits rb;
    unsigned c = __ldg(M + y * WPR + w);
    unsigned prev = (w > 0)   ? __ldg(M + y * WPR + w - 1) : 0u;
    unsigned next = (w < 15)  ? __ldg(M + y * WPR + w + 1) : 0u;
    unsigned Lc = (w > 0)  ? __funnelshift_l(prev, c, 1) : ((c << 1) | (c & 1u));
    unsigned Rc = (w < 15) ? __funnelshift_r(c, next, 1) : ((c >> 1) | (c & 0x80000000u));
    unsigned QL = Lc & c;
    if (w == 0) QL = (QL & ~1u) | (c & Rc & 1u);   // col0: quad cols {0,1}
    rb.C = c; rb.Lc = Lc; rb.Rc = Rc; rb.QL = QL; rb.QR = c & Rc;
    return rb;
}

__global__ void lbp_bits_kernel() {
    int gid = blockIdx.x * blockDim.x + threadIdx.x;   // NIMG*8192 threads
    int img = gid >> 13;
    int rem = gid & 8191;
    int r = rem >> 4;
    int w = rem & 15;
    const unsigned* __restrict__ M = g_mask + img * 8192;

    int rm = max(r - 1, 0);
    int rp = min(r + 1, HH - 1);
    RowBits Rr  = rowbits(M, r,  w);
    RowBits Rrp = rowbits(M, rp, w);
    RowBits Rpm0, Rpm1;         // row pair for dr = -0.707: {clamp(r-1), clamp(r-1)+1}
    if (r == 0) { Rpm0 = Rr; Rpm1 = Rrp; }
    else        { Rpm0 = rowbits(M, rm, w); Rpm1 = Rr; }
    unsigned Crm = (r == 0) ? Rr.C : Rpm0.C;   // C(clamp(r-1))

    unsigned b[8];
    b[0] = Rr.Rc;                 // (0, +1)
    b[2] = Crm;                   // (-1, 0)
    b[4] = Rr.Lc;                 // (0, -1)
    b[6] = Rrp.C;                 // (+1, 0)
    b[1] = Rpm0.QR & Rpm1.QR;     // (-.707, +.707)
    b[3] = Rpm0.QL & Rpm1.QL;     // (-.707, -.707)
    b[5] = Rr.QL & Rrp.QL;        // (+.707, -.707)
    b[7] = Rr.QR & Rrp.QR;        // (+.707, +.707)

    unsigned s0, s1, s2, s3;
    sum8(b, s0, s1, s2, s3);
    unsigned ok_s = ~(s3 | (s2 & (s1 | s0)));     // sum < 5

    unsigned ch[8];
#pragma unroll
    for (int k = 0; k < 8; k++) ch[k] = b[k] ^ b[(k + 7) & 7];
    unsigned c0, c1, c2, c3;
    sum8(ch, c0, c1, c2, c3);
    unsigned ok_ch = ~(c2 | c3);                  // changes <= 2 (changes is even)

    g_fbits[gid] = Rr.C & ok_s & ok_ch;           // center must be 1
}

// ---------------- 3) ordered compaction from flag bitmask ------------------------
__global__ void __launch_bounds__(1024) select_kernel() {
    const int img = blockIdx.x;
    __shared__ int s_wtot[32];
    __shared__ int s_woff[32];
    const int tid = threadIdx.x, lane = tid & 31, wrp = tid >> 5;

    g_pts[img][tid] = make_float2(0.0f, 0.0f);    // zero-pad
    g_pti[img][tid] = 0u;

    const unsigned* __restrict__ F = g_fbits + img * 8192;
    unsigned wv[8];
    int cnt = 0;
    const int w0 = tid * 8;
#pragma unroll
    for (int i = 0; i < 8; i++) { wv[i] = __ldg(F + w0 + i); cnt += __popc(wv[i]); }

    // block-wide exclusive prefix
    int incl = cnt;
#pragma unroll
    for (int d = 1; d < 32; d <<= 1) {
        int n = __shfl_up_sync(0xffffffffu, incl, d);
        if (lane >= d) incl += n;
    }
    if (lane == 31) s_wtot[wrp] = incl;
    __syncthreads();
    if (wrp == 0) {
        int t = s_wtot[lane];
        int ti = t;
#pragma unroll
        for (int d = 1; d < 32; d <<= 1) {
            int n = __shfl_up_sync(0xffffffffu, ti, d);
            if (lane >= d) ti += n;
        }
        s_woff[lane] = ti - t;
    }
    __syncthreads();
    int rank = s_woff[wrp] + (incl - cnt);

    if (rank < KP && cnt > 0) {
#pragma unroll
        for (int i = 0; i < 8; i++) {
            unsigned m = wv[i];
            int pbase = (w0 + i) << 5;
            while (m && rank < KP) {
                int b = __ffs(m) - 1;
                m &= m - 1;
                int pp = pbase + b;
                int rr = pp >> 9, cc = pp & 511;
                g_pts[img][rank] = make_float2((float)rr, (float)cc);
                g_pti[img][rank] = ((unsigned)rr << 16) | (unsigned)cc;
                rank++;
            }
            if (rank >= KP) break;
        }
    }
}

// ---------------- 4) Prim's MST: coords ride the reduction -----------------------
// key = dx^2+dy^2+idx on x32-scaled coords == 1024*d2+idx exactly (same order &
// ties as reference float-sqrt argmin; keys are UNIQUE). Real keys < 2^29.
// Retired nodes: px=SENTX, key forced to sentinel cand in [8.79e8,2.39e9] --
// never wins while any active warp exists. Each warp publishes BOTH its min key
// and the packed xy of that node (written by the unique matching lane), so the
// post-barrier path needs no second s_xy[j] lookup: one parallel LDS of two
// 8-word arrays + a paired min-tree yields (key, xy) of the block winner.
// Retired warps may publish stale xy -- provably never selected, never read.
__global__ void __launch_bounds__(T_MST) mst_kernel() {
    const int img = blockIdx.x;
    __shared__ unsigned s_xy[KP];
    __shared__ __align__(16) unsigned s_red[2][8];
    __shared__ __align__(16) unsigned s_rxy[2][8];

    const int tid = threadIdx.x;
    const int lane = tid & 31;
    const int wrp = tid >> 5;

    for (int i = tid; i < KP; i += T_MST) s_xy[i] = g_pti[img][i] << 5;  // scaled packed
    __syncthreads();

    unsigned px[NPT], py[NPT], xyp[NPT], key[NPT];
    int src[NPT];
    const int base = tid * NPT;
    {
        const unsigned xy0 = s_xy[0];
        const unsigned jx0 = xy0 >> 16, jy0 = xy0 & 0xffffu;
#pragma unroll
        for (int q = 0; q < NPT; q++) {
            unsigned v = s_xy[base + q];
            xyp[q] = v;                            // packed, constant after init
            px[q] = v >> 16; py[q] = v & 0xffffu;
            unsigned dx = px[q] - jx0, dy = py[q] - jy0;
            key[q] = dx * dx + dy * dy + (unsigned)(base + q);
            src[q] = 0;
        }
    }
    if (tid == 0) { key[0] = UMAXV; px[0] = SENTX; }

    // initial argmin with xy tracking
    unsigned lmin = UMAXV, xymin = 0u;
#pragma unroll
    for (int q = 0; q < NPT; q++) {
        bool p = key[q] < lmin;
        lmin = p ? key[q] : lmin;
        xymin = p ? xyp[q] : xymin;
    }
    unsigned wm = __reduce_min_sync(0xffffffffu, lmin);
    if (lmin == wm) s_rxy[0][wrp] = xymin;        // unique matching lane (keys unique)
    if (lane == 0) s_red[0][wrp] = wm;
    __syncthreads();

    unsigned gm, gxy;
    {
        uint4 A = *(const uint4*)&s_red[0][0];
        uint4 B = *(const uint4*)&s_red[0][4];
        uint4 XA = *(const uint4*)&s_rxy[0][0];
        uint4 XB = *(const uint4*)&s_rxy[0][4];
        bool p;
        unsigned ka, xa, kb, xb, kc, xc, kd, xd, ke, xe, kf, xf;
        p = A.y < A.x; ka = p ? A.y : A.x; xa = p ? XA.y : XA.x;
        p = A.w < A.z; kb = p ? A.w : A.z; xb = p ? XA.w : XA.z;
        p = B.y < B.x; kc = p ? B.y : B.x; xc = p ? XB.y : XB.x;
        p = B.w < B.z; kd = p ? B.w : B.z; xd = p ? XB.w : XB.z;
        p = kb < ka;   ke = p ? kb : ka;   xe = p ? xb : xa;
        p = kd < kc;   kf = p ? kd : kc;   xf = p ? xd : xc;
        p = kf < ke;   gm = p ? kf : ke;   gxy = p ? xf : xe;
    }
    int j = (int)(gm & 1023u);

    int2* __restrict__ ep = g_edges[img];
#pragma unroll 1
    for (int step = 0; step < KP - 1; step++) {
        if (!__all_sync(0xffffffffu, lmin >= SKIPTHR)) {   // fully-retired warps skip all
            const int t = j - base;               // owner iff t in [0, NPT)
            // extract src[j&3] from PRE-update values via SEL tree
            int sA = (t == 1) ? src[1] : src[0];
            int sB = (t == 3) ? src[3] : src[2];
            int srcj = (t >= 2) ? sB : sA;
            if ((unsigned)t < (unsigned)NPT)      // single guarded STG.64
                ep[step] = make_int2(srcj, j);

            const unsigned jx = gxy >> 16, jy = gxy & 0xffffu;
            lmin = UMAXV;
#pragma unroll
            for (int q = 0; q < NPT; q++) {
                bool own = (t == q);
                px[q] = own ? SENTX : px[q];      // sentinel coordinate
                unsigned dx = px[q] - jx, dy = py[q] - jy;
                unsigned cand = dx * dx + dy * dy + (unsigned)(base + q);
                // merged retire: owner unconditionally takes cand (>= SKIPTHR)
                bool upd = own | (cand < key[q]); // strict <, keeps old src on tie
                key[q] = upd ? cand : key[q];
                src[q] = upd ? j : src[q];
                bool p = key[q] < lmin;           // argmin with xy tracking
                lmin = p ? key[q] : lmin;
                xymin = p ? xyp[q] : xymin;
            }
        }
        wm = __reduce_min_sync(0xffffffffu, lmin);
        const int par = (step + 1) & 1;           // double buffer: 1 barrier/iter
        if (lmin == wm) s_rxy[par][wrp] = xymin;  // unique in active warps; stale in
        if (lane == 0) s_red[par][wrp] = wm;      //   retired warps (never selected)
        __syncthreads();
        {
            uint4 A = *(const uint4*)&s_red[par][0];
            uint4 B = *(const uint4*)&s_red[par][4];
            uint4 XA = *(const uint4*)&s_rxy[par][0];
            uint4 XB = *(const uint4*)&s_rxy[par][4];
            bool p;
            unsigned ka, xa, kb, xb, kc, xc, kd, xd, ke, xe, kf, xf;
            p = A.y < A.x; ka = p ? A.y : A.x; xa = p ? XA.y : XA.x;
            p = A.w < A.z; kb = p ? A.w : A.z; xb = p ? XA.w : XA.z;
            p = B.y < B.x; kc = p ? B.y : B.x; xc = p ? XB.y : XB.x;
            p = B.w < B.z; kd = p ? B.w : B.z; xd = p ? XB.w : XB.z;
            p = kb < ka;   ke = p ? kb : ka;   xe = p ? xb : xa;
            p = kd < kc;   kf = p ? kd : kc;   xf = p ? xd : xc;
            p = kf < ke;   gm = p ? kf : ke;   gxy = p ? xf : xe;
        }
        j = (int)(gm & 1023u);
    }
}

// ---------------- 5) per-(sample,tree) loss: grid=16 -----------------------------
__device__ __forceinline__ float pdistf(float2 a, float2 b) {
    float dx = a.x - b.x, dy = a.y - b.y;
    return sqrtf(dx * dx + dy * dy);   // exact: integer d2 < 2^24
}

__global__ void __launch_bounds__(256) loss_kernel() {
    const int blk = blockIdx.x;        // 16 blocks: (sample s, tree t)
    const int s = blk >> 1;
    const int t = blk & 1;             // 0: pred-tree edges, 1: mask-tree edges

    const float2* __restrict__ Pp = g_pts[2 * s];
    const float2* __restrict__ Pm = g_pts[2 * s + 1];
    const int2*   __restrict__ E  = g_edges[2 * s + t];

    float acc = 0.0f;
    for (int e = threadIdx.x; e < KP - 1; e += 256) {
        int2 ee = E[e];
        float d = pdistf(Pp[ee.x], Pp[ee.y]) - pdistf(Pm[ee.x], Pm[ee.y]);
        acc += d * d;
    }
    __shared__ float red[256];
    const int tid = threadIdx.x;
    red[tid] = acc;
    __syncthreads();
#pragma unroll
    for (int w = 128; w; w >>= 1) {
        if (tid < w) red[tid] += red[tid + w];
        __syncthreads();
    }
    if (tid == 0) g_part[blk] = sqrtf(red[0]);
}

__global__ void final_kernel(float* __restrict__ out) {
    float t = 0.0f;
#pragma unroll
    for (int i = 0; i < NIMG; i++) t += g_part[i];
    out[0] = 0.1f * t / 8.0f;
}

// ---------------- launch ----------------
extern "C" void kernel_launch(void* const* d_in, const int* in_sizes, int n_in,
                              void* d_out, int out_size) {
    const float* model_output = (const float*)d_in[1];
    const float* labels       = (const float*)d_in[2];
    float* out = (float*)d_out;

    binarize_kernel<<<(NS * HW) / 256, 256>>>(model_output, labels);
    lbp_bits_kernel<<<(NIMG * 8192) / 256, 256>>>();
    select_kernel<<<NIMG, 1024>>>();
    mst_kernel<<<NIMG, T_MST>>>();
    loss_kernel<<<NIMG, 256>>>();
    final_kernel<<<1, 1>>>(out);
}

// round 11
// speedup vs baseline: 1.7776x; 1.7776x over previous
#include <cuda_runtime.h>
#include <stdint.h>

#define HH 512
#define WW 512
#define HW (HH*WW)
#define NS 8            // samples
#define NIMG 16         // samples * {pred, mask}
#define KP 1024         // points per set
#define T_MST 256
#define NPT 4           // nodes per MST thread
#define UMAXV 0xFFFFFFFFu
#define SENTX 46000u    // retired-node x (scaled); cands land in [8.79e8, 2.39e9]
#define SKIPTHR 0x20000000u  // 2^29: real keys <= 5.348e8 < 2^29; sentinel cands above
#define WPR 16          // 512/32 words per row

// ---------------- scratch (static device globals; no allocation) ----------------
__device__ unsigned g_mask[NIMG * 8192];          // binarized bitmasks (512x512 bits)
__device__ float2   g_pts[NIMG][KP];              // selected points (r, c) float
__device__ unsigned g_pti[NIMG][KP];              // packed int coords (r<<16)|c
__device__ int2     g_edges[NIMG][KP - 1];        // MST edges (src, j)
__device__ float    g_part[NIMG];                 // per-(sample,tree) partial norms

// ---------------- 1) binarize -> bitmasks ---------------------------------------
__global__ void binarize_kernel(const float* __restrict__ mo, const float* __restrict__ lb) {
    int gid = blockIdx.x * blockDim.x + threadIdx.x;   // exactly NS*HW threads
    int s = gid >> 18;
    int p = gid & (HW - 1);
    unsigned bp = __ballot_sync(0xffffffffu, __ldg(mo + gid) > 0.0f);  // sigmoid>0.5 <=> x>0
    unsigned bm = __ballot_sync(0xffffffffu, __ldg(lb + gid) > 0.5f);
    if ((threadIdx.x & 31) == 0) {
        int w = p >> 5;
        g_mask[(2 * s)     * 8192 + w] = bp;
        g_mask[(2 * s + 1) * 8192 + w] = bm;
    }
}

// ---------------- 2) fused uniform-LBP + ordered compaction ---------------------
// For binary imgs: center==0 -> never flagged. center==1 -> bit_k = AND of the
// (edge-clamped) bilinear taps: even k = single neighbor, odd k = 2x2 quad.
__device__ __forceinline__ unsigned maj3(unsigned a, unsigned b, unsigned c) {
    return (a & b) | (c & (a ^ b));
}
__device__ __forceinline__ void sum8(const unsigned b[8],
                                     unsigned& s0, unsigned& s1, unsigned& s2, unsigned& s3) {
    unsigned t0 = b[0] ^ b[1], c0 = b[0] & b[1];
    unsigned t1 = b[2] ^ b[3], c1 = b[2] & b[3];
    unsigned t2 = b[4] ^ b[5], c2 = b[4] & b[5];
    unsigned t3 = b[6] ^ b[7], c3 = b[6] & b[7];
    unsigned u0 = t0 ^ t1, d0 = t0 & t1;
    unsigned u1 = t2 ^ t3, d1 = t2 & t3;
    s0 = u0 ^ u1;
    unsigned e0 = u0 & u1;
    unsigned p0 = c0 ^ c1 ^ c2, q0 = maj3(c0, c1, c2);
    unsigned p1 = c3 ^ d0 ^ d1, q1 = maj3(c3, d0, d1);
    s1 = p0 ^ p1 ^ e0;
    unsigned q2 = maj3(p0, p1, e0);
    s2 = q0 ^ q1 ^ q2;
    s3 = maj3(q0, q1, q2);
}

struct RowBits { unsigned C, Lc, Rc, QL, QR; };

__device__ __forceinline__ RowBits rowbits_s(const unsigned* s_m, int y, int w) {
    RowBits rb;
    unsigned c = s_m[y * WPR + w];
    unsigned prev = (w > 0)   ? s_m[y * WPR + w - 1] : 0u;
    unsigned next = (w < 15)  ? s_m[y * WPR + w + 1] : 0u;
    unsigned Lc = (w > 0)  ? __funnelshift_l(prev, c, 1) : ((c << 1) | (c & 1u));
    unsigned Rc = (w < 15) ? __funnelshift_r(c, next, 1) : ((c >> 1) | (c & 0x80000000u));
    unsigned QL = Lc & c;
    if (w == 0) QL = (QL & ~1u) | (c & Rc & 1u);   // col0: quad cols {0,1}
    rb.C = c; rb.Lc = Lc; rb.Rc = Rc; rb.QL = QL; rb.QR = c & Rc;
    return rb;
}

__device__ __forceinline__ unsigned lbp_word(const unsigned* s_m, int r, int w) {
    int rm = max(r - 1, 0);
    int rp = min(r + 1, HH - 1);
    RowBits Rr  = rowbits_s(s_m, r,  w);
    RowBits Rrp = rowbits_s(s_m, rp, w);
    RowBits Rpm0, Rpm1;         // row pair for dr = -0.707: {clamp(r-1), clamp(r-1)+1}
    if (r == 0) { Rpm0 = Rr; Rpm1 = Rrp; }
    else        { Rpm0 = rowbits_s(s_m, rm, w); Rpm1 = Rr; }
    unsigned Crm = (r == 0) ? Rr.C : Rpm0.C;   // C(clamp(r-1))

    unsigned b[8];
    b[0] = Rr.Rc;                 // (0, +1)
    b[2] = Crm;                   // (-1, 0)
    b[4] = Rr.Lc;                 // (0, -1)
    b[6] = Rrp.C;                 // (+1, 0)
    b[1] = Rpm0.QR & Rpm1.QR;     // (-.707, +.707)
    b[3] = Rpm0.QL & Rpm1.QL;     // (-.707, -.707)
    b[5] = Rr.QL & Rrp.QL;        // (+.707, -.707)
    b[7] = Rr.QR & Rrp.QR;        // (+.707, +.707)

    unsigned s0, s1, s2, s3;
    sum8(b, s0, s1, s2, s3);
    unsigned ok_s = ~(s3 | (s2 & (s1 | s0)));     // sum < 5

    unsigned ch[8];
#pragma unroll
    for (int k = 0; k < 8; k++) ch[k] = b[k] ^ b[(k + 7) & 7];
    unsigned c0, c1, c2, c3;
    sum8(ch, c0, c1, c2, c3);
    unsigned ok_ch = ~(c2 | c3);                  // changes <= 2 (changes is even)

    return Rr.C & ok_s & ok_ch;                   // center must be 1
}

__global__ void __launch_bounds__(1024) lbp_select_kernel() {
    const int img = blockIdx.x;
    __shared__ unsigned s_m[8192];                // full 512x512 bitmask, 32 KB
    __shared__ int s_wtot[32];
    __shared__ int s_woff[32];
    const int tid = threadIdx.x, lane = tid & 31, wrp = tid >> 5;

    // stage mask in smem (2 x uint4 per thread) + zero-pad outputs
    {
        const uint4* __restrict__ M4 = (const uint4*)(g_mask + img * 8192);
        uint4 a = __ldg(M4 + tid * 2);
        uint4 b = __ldg(M4 + tid * 2 + 1);
        *(uint4*)&s_m[tid * 8]     = a;
        *(uint4*)&s_m[tid * 8 + 4] = b;
    }
    g_pts[img][tid] = make_float2(0.0f, 0.0f);
    g_pti[img][tid] = 0u;
    __syncthreads();

    // compute this thread's 8 flag words (pixels tid*256 .. tid*256+255)
    unsigned wv[8];
    int cnt = 0;
    const int w0 = tid * 8;
#pragma unroll
    for (int i = 0; i < 8; i++) {
        int wi = w0 + i;
        wv[i] = lbp_word(s_m, wi >> 4, wi & 15);
        cnt += __popc(wv[i]);
    }

    // block-wide exclusive prefix
    int incl = cnt;
#pragma unroll
    for (int d = 1; d < 32; d <<= 1) {
        int n = __shfl_up_sync(0xffffffffu, incl, d);
        if (lane >= d) incl += n;
    }
    if (lane == 31) s_wtot[wrp] = incl;
    __syncthreads();
    if (wrp == 0) {
        int t = s_wtot[lane];
        int ti = t;
#pragma unroll
        for (int d = 1; d < 32; d <<= 1) {
            int n = __shfl_up_sync(0xffffffffu, ti, d);
            if (lane >= d) ti += n;
        }
        s_woff[lane] = ti - t;
    }
    __syncthreads();
    int rank = s_woff[wrp] + (incl - cnt);

    // ordered emission (row-major; rank order == pixel order)
    if (rank < KP && cnt > 0) {
#pragma unroll
        for (int i = 0; i < 8; i++) {
            unsigned m = wv[i];
            int pbase = (w0 + i) << 5;
            while (m && rank < KP) {
                int b = __ffs(m) - 1;
                m &= m - 1;
                int pp = pbase + b;
                int rr = pp >> 9, cc = pp & 511;
                g_pts[img][rank] = make_float2((float)rr, (float)cc);
                g_pti[img][rank] = ((unsigned)rr << 16) | (unsigned)cc;
                rank++;
            }
            if (rank >= KP) break;
        }
    }
}

// ---------------- 3) Prim's MST: 256 thr x 4 nodes, merged retire (R9) -----------
// Coords scaled x32, packed in smem (v<<5: no field carry). key = dx^2+dy^2+idx
// == 1024*d2 + idx exactly: same ordering and ties as the reference float-sqrt
// argmin. Real keys <= 5.348e8 < 2^29. Retirement MERGED into the update: the
// owner sets px=SENTX and forces key = cand (sentinel-distance in [8.79e8,
// 2.39e9] -- above every real key, below 2^32), so retired nodes never win.
// Warp with all lmin >= 2^29 is fully retired, can never own j, skips all.
// 256 threads = 2 warps/SMSP hides the redux->STS->BAR->LDS chain.
__global__ void __launch_bounds__(T_MST) mst_kernel() {
    const int img = blockIdx.x;
    __shared__ unsigned s_xy[KP];
    __shared__ __align__(16) unsigned s_red[2][8];

    const int tid = threadIdx.x;
    const int lane = tid & 31;
    const int wrp = tid >> 5;

    for (int i = tid; i < KP; i += T_MST) s_xy[i] = g_pti[img][i] << 5;  // scaled packed
    __syncthreads();

    unsigned px[NPT], py[NPT], key[NPT];
    int src[NPT];
    const int base = tid * NPT;
    {
        const unsigned xy0 = s_xy[0];
        const unsigned jx = xy0 >> 16, jy = xy0 & 0xffffu;
#pragma unroll
        for (int q = 0; q < NPT; q++) {
            unsigned v = s_xy[base + q];
            px[q] = v >> 16; py[q] = v & 0xffffu;
            unsigned dx = px[q] - jx, dy = py[q] - jy;
            key[q] = dx * dx + dy * dy + (unsigned)(base + q);
            src[q] = 0;
        }
    }
    if (tid == 0) { key[0] = UMAXV; px[0] = SENTX; }

    unsigned lmin = UMAXV;
#pragma unroll
    for (int q = 0; q < NPT; q++) lmin = min(lmin, key[q]);
    unsigned wm = __reduce_min_sync(0xffffffffu, lmin);
    if (lane == 0) s_red[0][wrp] = wm;
    __syncthreads();
    uint4 A = *(const uint4*)&s_red[0][0];
    uint4 B = *(const uint4*)&s_red[0][4];
    unsigned gm = min(min(min(A.x, A.y), min(A.z, A.w)),
                      min(min(B.x, B.y), min(B.z, B.w)));
    int j = (int)(gm & 1023u);
    unsigned jxy = s_xy[j];                       // pipelined fetch

    int2* __restrict__ ep = g_edges[img];
#pragma unroll 1
    for (int step = 0; step < KP - 1; step++) {
        if (!__all_sync(0xffffffffu, lmin >= SKIPTHR)) {   // fully-retired warps skip all
            const int t = j - base;               // owner iff t in [0, NPT)
            // extract src[j&3] from PRE-update values via SEL tree
            int sA = (t == 1) ? src[1] : src[0];
            int sB = (t == 3) ? src[3] : src[2];
            int srcj = (t >= 2) ? sB : sA;
            if ((unsigned)t < (unsigned)NPT)      // single guarded STG.64
                ep[step] = make_int2(srcj, j);

            const unsigned jx = jxy >> 16, jy = jxy & 0xffffu;
            lmin = UMAXV;
#pragma unroll
            for (int q = 0; q < NPT; q++) {
                bool own = (t == q);
                px[q] = own ? SENTX : px[q];      // sentinel coordinate
                unsigned dx = px[q] - jx, dy = py[q] - jy;
                unsigned cand = dx * dx + dy * dy + (unsigned)(base + q);
                // merged retire: owner unconditionally takes cand (>= SKIPTHR)
                bool upd = own | (cand < key[q]); // strict <, keeps old src on tie
                key[q] = upd ? cand : key[q];
                src[q] = upd ? j : src[q];
                lmin = min(lmin, key[q]);
            }
        }
        wm = __reduce_min_sync(0xffffffffu, lmin);
        const int par = (step + 1) & 1;           // double buffer: 1 barrier/iter
        if (lane == 0) s_red[par][wrp] = wm;
        __syncthreads();
        A = *(const uint4*)&s_red[par][0];
        B = *(const uint4*)&s_red[par][4];
        gm = min(min(min(A.x, A.y), min(A.z, A.w)),
                 min(min(B.x, B.y), min(B.z, B.w)));
        j = (int)(gm & 1023u);
        jxy = s_xy[j];                            // prefetch for next iteration
    }
}

// ---------------- 4) per-(sample,tree) loss: grid=16 -----------------------------
__device__ __forceinline__ float pdistf(float2 a, float2 b) {
    float dx = a.x - b.x, dy = a.y - b.y;
    return sqrtf(dx * dx + dy * dy);   // exact: integer d2 < 2^24
}

__global__ void __launch_bounds__(256) loss_kernel() {
    const int blk = blockIdx.x;        // 16 blocks: (sample s, tree t)
    const int s = blk >> 1;
    const int t = blk & 1;             // 0: pred-tree edges, 1: mask-tree edges

    const float2* __restrict__ Pp = g_pts[2 * s];
    const float2* __restrict__ Pm = g_pts[2 * s + 1];
    const int2*   __restrict__ E  = g_edges[2 * s + t];

    float acc = 0.0f;
    for (int e = threadIdx.x; e < KP - 1; e += 256) {
        int2 ee = E[e];
        float d = pdistf(Pp[ee.x], Pp[ee.y]) - pdistf(Pm[ee.x], Pm[ee.y]);
        acc += d * d;
    }
    __shared__ float red[256];
    const int tid = threadIdx.x;
    red[tid] = acc;
    __syncthreads();
#pragma unroll
    for (int w = 128; w; w >>= 1) {
        if (tid < w) red[tid] += red[tid + w];
        __syncthreads();
    }
    if (tid == 0) g_part[blk] = sqrtf(red[0]);
}

__global__ void final_kernel(float* __restrict__ out) {
    float t = 0.0f;
#pragma unroll
    for (int i = 0; i < NIMG; i++) t += g_part[i];
    out[0] = 0.1f * t / 8.0f;
}

// ---------------- launch ----------------
extern "C" void kernel_launch(void* const* d_in, const int* in_sizes, int n_in,
                              void* d_out, int out_size) {
    const float* model_output = (const float*)d_in[1];
    const float* labels       = (const float*)d_in[2];
    float* out = (float*)d_out;

    binarize_kernel<<<(NS * HW) / 256, 256>>>(model_output, labels);
    lbp_select_kernel<<<NIMG, 1024>>>();
    mst_kernel<<<NIMG, T_MST>>>();
    loss_kernel<<<NIMG, 256>>>();
    final_kernel<<<1, 1>>>(out);
}

// round 12
// speedup vs baseline: 1.8195x; 1.0236x over previous
#include <cuda_runtime.h>
#include <stdint.h>

#define HH 512
#define WW 512
#define HW (HH*WW)
#define NS 8            // samples
#define NIMG 16         // samples * {pred, mask}
#define KP 1024         // points per set
#define T_MST 256
#define NPT 4           // nodes per MST thread
#define UMAXV 0xFFFFFFFFu
#define SENTX 46000u    // retired-node x (scaled); cands land in [8.79e8, 2.39e9]
#define SKIPTHR 0x20000000u  // 2^29: real keys <= 5.348e8 < 2^29; sentinel cands above
#define WPR 16          // 512/32 words per row

// ---------------- scratch (static device globals; no allocation) ----------------
__device__ unsigned g_mask[NIMG * 8192];          // binarized bitmasks (512x512 bits)
__device__ unsigned g_fbits[NIMG * 8192];         // lbp<THR flag bitmasks
__device__ float2   g_pts[NIMG][KP];              // selected points (r, c) float
__device__ unsigned g_pti[NIMG][KP];              // packed int coords (r<<16)|c
__device__ int2     g_edges[NIMG][KP - 1];        // MST edges (src, j)
__device__ float    g_part[NIMG];                 // per-(sample,tree) partial norms

// ---------------- 1) binarize -> bitmasks ---------------------------------------
__global__ void binarize_kernel(const float* __restrict__ mo, const float* __restrict__ lb) {
    int gid = blockIdx.x * blockDim.x + threadIdx.x;   // exactly NS*HW threads
    int s = gid >> 18;
    int p = gid & (HW - 1);
    unsigned bp = __ballot_sync(0xffffffffu, __ldg(mo + gid) > 0.0f);  // sigmoid>0.5 <=> x>0
    unsigned bm = __ballot_sync(0xffffffffu, __ldg(lb + gid) > 0.5f);
    if ((threadIdx.x & 31) == 0) {
        int w = p >> 5;
        g_mask[(2 * s)     * 8192 + w] = bp;
        g_mask[(2 * s + 1) * 8192 + w] = bm;
    }
}

// ---------------- 2) uniform LBP on bitmasks (exact) ----------------------------
__device__ __forceinline__ unsigned maj3(unsigned a, unsigned b, unsigned c) {
    return (a & b) | (c & (a ^ b));
}
__device__ __forceinline__ void sum8(const unsigned b[8],
                                     unsigned& s0, unsigned& s1, unsigned& s2, unsigned& s3) {
    unsigned t0 = b[0] ^ b[1], c0 = b[0] & b[1];
    unsigned t1 = b[2] ^ b[3], c1 = b[2] & b[3];
    unsigned t2 = b[4] ^ b[5], c2 = b[4] & b[5];
    unsigned t3 = b[6] ^ b[7], c3 = b[6] & b[7];
    unsigned u0 = t0 ^ t1, d0 = t0 & t1;
    unsigned u1 = t2 ^ t3, d1 = t2 & t3;
    s0 = u0 ^ u1;
    unsigned e0 = u0 & u1;
    unsigned p0 = c0 ^ c1 ^ c2, q0 = maj3(c0, c1, c2);
    unsigned p1 = c3 ^ d0 ^ d1, q1 = maj3(c3, d0, d1);
    s1 = p0 ^ p1 ^ e0;
    unsigned q2 = maj3(p0, p1, e0);
    s2 = q0 ^ q1 ^ q2;
    s3 = maj3(q0, q1, q2);
}

struct RowBits { unsigned C, Lc, Rc, QL, QR; };

__device__ __forceinline__ RowBits rowbits(const unsigned* __restrict__ M, int y, int w) {
    RowBits rb;
    unsigned c = __ldg(M + y * WPR + w);
    unsigned prev = (w > 0)   ? __ldg(M + y * WPR + w - 1) : 0u;
    unsigned next = (w < 15)  ? __ldg(M + y * WPR + w + 1) : 0u;
    unsigned Lc = (w > 0)  ? __funnelshift_l(prev, c, 1) : ((c << 1) | (c & 1u));
    unsigned Rc = (w < 15) ? __funnelshift_r(c, next, 1) : ((c >> 1) | (c & 0x80000000u));
    unsigned QL = Lc & c;
    if (w == 0) QL = (QL & ~1u) | (c & Rc & 1u);   // col0: quad cols {0,1}
    rb.C = c; rb.Lc = Lc; rb.Rc = Rc; rb.QL = QL; rb.QR = c & Rc;
    return rb;
}

__global__ void lbp_bits_kernel() {
    int gid = blockIdx.x * blockDim.x + threadIdx.x;   // NIMG*8192 threads
    int img = gid >> 13;
    int rem = gid & 8191;
    int r = rem >> 4;
    int w = rem & 15;
    const unsigned* __restrict__ M = g_mask + img * 8192;

    int rm = max(r - 1, 0);
    int rp = min(r + 1, HH - 1);
    RowBits Rr  = rowbits(M, r,  w);
    RowBits Rrp = rowbits(M, rp, w);
    RowBits Rpm0, Rpm1;         // row pair for dr = -0.707: {clamp(r-1), clamp(r-1)+1}
    if (r == 0) { Rpm0 = Rr; Rpm1 = Rrp; }
    else        { Rpm0 = rowbits(M, rm, w); Rpm1 = Rr; }
    unsigned Crm = (r == 0) ? Rr.C : Rpm0.C;   // C(clamp(r-1))

    unsigned b[8];
    b[0] = Rr.Rc;                 // (0, +1)
    b[2] = Crm;                   // (-1, 0)
    b[4] = Rr.Lc;                 // (0, -1)
    b[6] = Rrp.C;                 // (+1, 0)
    b[1] = Rpm0.QR & Rpm1.QR;     // (-.707, +.707)
    b[3] = Rpm0.QL & Rpm1.QL;     // (-.707, -.707)
    b[5] = Rr.QL & Rrp.QL;        // (+.707, -.707)
    b[7] = Rr.QR & Rrp.QR;        // (+.707, +.707)

    unsigned s0, s1, s2, s3;
    sum8(b, s0, s1, s2, s3);
    unsigned ok_s = ~(s3 | (s2 & (s1 | s0)));     // sum < 5

    unsigned ch[8];
#pragma unroll
    for (int k = 0; k < 8; k++) ch[k] = b[k] ^ b[(k + 7) & 7];
    unsigned c0, c1, c2, c3;
    sum8(ch, c0, c1, c2, c3);
    unsigned ok_ch = ~(c2 | c3);                  // changes <= 2 (changes is even)

    g_fbits[gid] = Rr.C & ok_s & ok_ch;           // center must be 1
}

// ---------------- 3) ordered compaction from flag bitmask ------------------------
__global__ void __launch_bounds__(1024) select_kernel() {
    const int img = blockIdx.x;
    __shared__ int s_wtot[32];
    __shared__ int s_woff[32];
    const int tid = threadIdx.x, lane = tid & 31, wrp = tid >> 5;

    g_pts[img][tid] = make_float2(0.0f, 0.0f);    // zero-pad
    g_pti[img][tid] = 0u;

    const unsigned* __restrict__ F = g_fbits + img * 8192;
    unsigned wv[8];
    int cnt = 0;
    const int w0 = tid * 8;
#pragma unroll
    for (int i = 0; i < 8; i++) { wv[i] = __ldg(F + w0 + i); cnt += __popc(wv[i]); }

    // block-wide exclusive prefix
    int incl = cnt;
#pragma unroll
    for (int d = 1; d < 32; d <<= 1) {
        int n = __shfl_up_sync(0xffffffffu, incl, d);
        if (lane >= d) incl += n;
    }
    if (lane == 31) s_wtot[wrp] = incl;
    __syncthreads();
    if (wrp == 0) {
        int t = s_wtot[lane];
        int ti = t;
#pragma unroll
        for (int d = 1; d < 32; d <<= 1) {
            int n = __shfl_up_sync(0xffffffffu, ti, d);
            if (lane >= d) ti += n;
        }
        s_woff[lane] = ti - t;
    }
    __syncthreads();
    int rank = s_woff[wrp] + (incl - cnt);

    if (rank < KP && cnt > 0) {
#pragma unroll
        for (int i = 0; i < 8; i++) {
            unsigned m = wv[i];
            int pbase = (w0 + i) << 5;
            while (m && rank < KP) {
                int b = __ffs(m) - 1;
                m &= m - 1;
                int pp = pbase + b;
                int rr = pp >> 9, cc = pp & 511;
                g_pts[img][rank] = make_float2((float)rr, (float)cc);
                g_pti[img][rank] = ((unsigned)rr << 16) | (unsigned)cc;
                rank++;
            }
            if (rank >= KP) break;
        }
    }
}

// ---------------- 4) Prim's MST: R9 structure + deferred skip vote ---------------
// Coords scaled x32, packed in smem (v<<5: no field carry). key = dx^2+dy^2+idx
// == 1024*d2 + idx exactly: same ordering and ties as the reference float-sqrt
// argmin. Real keys <= 5.348e8 < 2^29. Retirement MERGED into the update: the
// owner sets px=SENTX and forces key = cand (sentinel-distance in [8.79e8,
// 2.39e9] -- above every real key, below 2^32), so retired nodes never win.
// Skip vote is computed at loop BOTTOM (overlaps the barrier wait) -- it only
// needs this iteration's lmin. A fully-retired warp (all keys >= 2^29) can
// never own the selected j, so skipping retire+emit+update is safe.
__global__ void __launch_bounds__(T_MST) mst_kernel() {
    const int img = blockIdx.x;
    __shared__ unsigned s_xy[KP];
    __shared__ __align__(16) unsigned s_red[2][8];

    const int tid = threadIdx.x;
    const int lane = tid & 31;
    const int wrp = tid >> 5;

    for (int i = tid; i < KP; i += T_MST) s_xy[i] = g_pti[img][i] << 5;  // scaled packed
    __syncthreads();

    unsigned px[NPT], py[NPT], key[NPT];
    int src[NPT];
    const int base = tid * NPT;
    {
        const unsigned xy0 = s_xy[0];
        const unsigned jx = xy0 >> 16, jy = xy0 & 0xffffu;
#pragma unroll
        for (int q = 0; q < NPT; q++) {
            unsigned v = s_xy[base + q];
            px[q] = v >> 16; py[q] = v & 0xffffu;
            unsigned dx = px[q] - jx, dy = py[q] - jy;
            key[q] = dx * dx + dy * dy + (unsigned)(base + q);
            src[q] = 0;
        }
    }
    if (tid == 0) { key[0] = UMAXV; px[0] = SENTX; }

    unsigned lmin = UMAXV;
#pragma unroll
    for (int q = 0; q < NPT; q++) lmin = min(lmin, key[q]);
    bool skip = __all_sync(0xffffffffu, lmin >= SKIPTHR);   // precomputed vote
    unsigned wm = __reduce_min_sync(0xffffffffu, lmin);
    if (lane == 0) s_red[0][wrp] = wm;
    __syncthreads();
    uint4 A = *(const uint4*)&s_red[0][0];
    uint4 B = *(const uint4*)&s_red[0][4];
    unsigned gm = min(min(min(A.x, A.y), min(A.z, A.w)),
                      min(min(B.x, B.y), min(B.z, B.w)));
    int j = (int)(gm & 1023u);
    unsigned jxy = s_xy[j];                       // pipelined fetch

    int2* __restrict__ ep = g_edges[img];
#pragma unroll 1
    for (int step = 0; step < KP - 1; step++) {
        if (!skip) {                              // vote from PREVIOUS iteration
            const int t = j - base;               // owner iff t in [0, NPT)
            // extract src[j&3] from PRE-update values via SEL tree
            int sA = (t == 1) ? src[1] : src[0];
            int sB = (t == 3) ? src[3] : src[2];
            int srcj = (t >= 2) ? sB : sA;

            const unsigned jx = jxy >> 16, jy = jxy & 0xffffu;
            lmin = UMAXV;
#pragma unroll
            for (int q = 0; q < NPT; q++) {
                bool own = (t == q);
                px[q] = own ? SENTX : px[q];      // sentinel coordinate
                unsigned dx = px[q] - jx, dy = py[q] - jy;
                unsigned cand = dx * dx + dy * dy + (unsigned)(base + q);
                // merged retire: owner unconditionally takes cand (>= SKIPTHR)
                bool upd = own | (cand < key[q]); // strict <, keeps old src on tie
                key[q] = upd ? cand : key[q];
                src[q] = upd ? j : src[q];
                lmin = min(lmin, key[q]);
            }
            if ((unsigned)t < (unsigned)NPT)      // fire-and-forget, off the chain
                ep[step] = make_int2(srcj, j);
        }
        skip = __all_sync(0xffffffffu, lmin >= SKIPTHR);   // overlaps barrier wait
        wm = __reduce_min_sync(0xffffffffu, lmin);
        const int par = (step + 1) & 1;           // double buffer: 1 barrier/iter
        if (lane == 0) s_red[par][wrp] = wm;
        __syncthreads();
        A = *(const uint4*)&s_red[par][0];
        B = *(const uint4*)&s_red[par][4];
        gm = min(min(min(A.x, A.y), min(A.z, A.w)),
                 min(min(B.x, B.y), min(B.z, B.w)));
        j = (int)(gm & 1023u);
        jxy = s_xy[j];                            // prefetch for next iteration
    }
}

// ---------------- 5) per-(sample,tree) loss: grid=16 -----------------------------
__device__ __forceinline__ float pdistf(float2 a, float2 b) {
    float dx = a.x - b.x, dy = a.y - b.y;
    return sqrtf(dx * dx + dy * dy);   // exact: integer d2 < 2^24
}

__global__ void __launch_bounds__(256) loss_kernel() {
    const int blk = blockIdx.x;        // 16 blocks: (sample s, tree t)
    const int s = blk >> 1;
    const int t = blk & 1;             // 0: pred-tree edges, 1: mask-tree edges

    const float2* __restrict__ Pp = g_pts[2 * s];
    const float2* __restrict__ Pm = g_pts[2 * s + 1];
    const int2*   __restrict__ E  = g_edges[2 * s + t];

    float acc = 0.0f;
    for (int e = threadIdx.x; e < KP - 1; e += 256) {
        int2 ee = E[e];
        float d = pdistf(Pp[ee.x], Pp[ee.y]) - pdistf(Pm[ee.x], Pm[ee.y]);
        acc += d * d;
    }
    __shared__ float red[256];
    const int tid = threadIdx.x;
    red[tid] = acc;
    __syncthreads();
#pragma unroll
    for (int w = 128; w; w >>= 1) {
        if (tid < w) red[tid] += red[tid + w];
        __syncthreads();
    }
    if (tid == 0) g_part[blk] = sqrtf(red[0]);
}

__global__ void final_kernel(float* __restrict__ out) {
    float t = 0.0f;
#pragma unroll
    for (int i = 0; i < NIMG; i++) t += g_part[i];
    out[0] = 0.1f * t / 8.0f;
}

// ---------------- launch ----------------
extern "C" void kernel_launch(void* const* d_in, const int* in_sizes, int n_in,
                              void* d_out, int out_size) {
    const float* model_output = (const float*)d_in[1];
    const float* labels       = (const float*)d_in[2];
    float* out = (float*)d_out;

    binarize_kernel<<<(NS * HW) / 256, 256>>>(model_output, labels);
    lbp_bits_kernel<<<(NIMG * 8192) / 256, 256>>>();
    select_kernel<<<NIMG, 1024>>>();
    mst_kernel<<<NIMG, T_MST>>>();
    loss_kernel<<<NIMG, 256>>>();
    final_kernel<<<1, 1>>>(out);
}

// round 13
// speedup vs baseline: 1.8452x; 1.0141x over previous
#include <cuda_runtime.h>
#include <stdint.h>

#define HH 512
#define WW 512
#define HW (HH*WW)
#define NS 8            // samples
#define NIMG 16         // samples * {pred, mask}
#define KP 1024         // points per set
#define T_MST 256
#define NPT 4           // nodes per MST thread
#define UMAXV 0xFFFFFFFFu
#define SENTX 46000u    // retired-node x (scaled); cands land in [8.79e8, 2.39e9]
#define SKIPTHR 0x20000000u  // 2^29: real keys <= 5.348e8 < 2^29; sentinel cands above
#define WPR 16          // 512/32 words per row

// ---------------- scratch (static device globals; no allocation) ----------------
__device__ unsigned g_mask[NIMG * 8192];          // binarized bitmasks (512x512 bits)
__device__ unsigned g_fbits[NIMG * 8192];         // lbp<THR flag bitmasks
__device__ float2   g_pts[NIMG][KP];              // selected points (r, c) float
__device__ unsigned g_pti[NIMG][KP];              // packed int coords (r<<16)|c
__device__ int2     g_edges[NIMG][KP - 1];        // MST edges (src, j)
__device__ float    g_part[NIMG];                 // per-(sample,tree) partial norms
__device__ unsigned g_cnt;                        // loss completion counter

// ---------------- 1) binarize -> bitmasks ---------------------------------------
__global__ void binarize_kernel(const float* __restrict__ mo, const float* __restrict__ lb) {
    int gid = blockIdx.x * blockDim.x + threadIdx.x;   // exactly NS*HW threads
    if (gid == 0) g_cnt = 0u;                          // reset loss counter each call
    int s = gid >> 18;
    int p = gid & (HW - 1);
    unsigned bp = __ballot_sync(0xffffffffu, __ldg(mo + gid) > 0.0f);  // sigmoid>0.5 <=> x>0
    unsigned bm = __ballot_sync(0xffffffffu, __ldg(lb + gid) > 0.5f);
    if ((threadIdx.x & 31) == 0) {
        int w = p >> 5;
        g_mask[(2 * s)     * 8192 + w] = bp;
        g_mask[(2 * s + 1) * 8192 + w] = bm;
    }
}

// ---------------- 2) uniform LBP on bitmasks (exact) ----------------------------
__device__ __forceinline__ unsigned maj3(unsigned a, unsigned b, unsigned c) {
    return (a & b) | (c & (a ^ b));
}
__device__ __forceinline__ void sum8(const unsigned b[8],
                                     unsigned& s0, unsigned& s1, unsigned& s2, unsigned& s3) {
    unsigned t0 = b[0] ^ b[1], c0 = b[0] & b[1];
    unsigned t1 = b[2] ^ b[3], c1 = b[2] & b[3];
    unsigned t2 = b[4] ^ b[5], c2 = b[4] & b[5];
    unsigned t3 = b[6] ^ b[7], c3 = b[6] & b[7];
    unsigned u0 = t0 ^ t1, d0 = t0 & t1;
    unsigned u1 = t2 ^ t3, d1 = t2 & t3;
    s0 = u0 ^ u1;
    unsigned e0 = u0 & u1;
    unsigned p0 = c0 ^ c1 ^ c2, q0 = maj3(c0, c1, c2);
    unsigned p1 = c3 ^ d0 ^ d1, q1 = maj3(c3, d0, d1);
    s1 = p0 ^ p1 ^ e0;
    unsigned q2 = maj3(p0, p1, e0);
    s2 = q0 ^ q1 ^ q2;
    s3 = maj3(q0, q1, q2);
}

struct RowBits { unsigned C, Lc, Rc, QL, QR; };

__device__ __forceinline__ RowBits rowbits(const unsigned* __restrict__ M, int y, int w) {
    RowBits rb;
    unsigned c = __ldg(M + y * WPR + w);
    unsigned prev = (w > 0)   ? __ldg(M + y * WPR + w - 1) : 0u;
    unsigned next = (w < 15)  ? __ldg(M + y * WPR + w + 1) : 0u;
    unsigned Lc = (w > 0)  ? __funnelshift_l(prev, c, 1) : ((c << 1) | (c & 1u));
    unsigned Rc = (w < 15) ? __funnelshift_r(c, next, 1) : ((c >> 1) | (c & 0x80000000u));
    unsigned QL = Lc & c;
    if (w == 0) QL = (QL & ~1u) | (c & Rc & 1u);   // col0: quad cols {0,1}
    rb.C = c; rb.Lc = Lc; rb.Rc = Rc; rb.QL = QL; rb.QR = c & Rc;
    return rb;
}

__global__ void lbp_bits_kernel() {
    int gid = blockIdx.x * blockDim.x + threadIdx.x;   // NIMG*8192 threads
    int img = gid >> 13;
    int rem = gid & 8191;
    int r = rem >> 4;
    int w = rem & 15;
    const unsigned* __restrict__ M = g_mask + img * 8192;

    int rm = max(r - 1, 0);
    int rp = min(r + 1, HH - 1);
    RowBits Rr  = rowbits(M, r,  w);
    RowBits Rrp = rowbits(M, rp, w);
    RowBits Rpm0, Rpm1;         // row pair for dr = -0.707: {clamp(r-1), clamp(r-1)+1}
    if (r == 0) { Rpm0 = Rr; Rpm1 = Rrp; }
    else        { Rpm0 = rowbits(M, rm, w); Rpm1 = Rr; }
    unsigned Crm = (r == 0) ? Rr.C : Rpm0.C;   // C(clamp(r-1))

    unsigned b[8];
    b[0] = Rr.Rc;                 // (0, +1)
    b[2] = Crm;                   // (-1, 0)
    b[4] = Rr.Lc;                 // (0, -1)
    b[6] = Rrp.C;                 // (+1, 0)
    b[1] = Rpm0.QR & Rpm1.QR;     // (-.707, +.707)
    b[3] = Rpm0.QL & Rpm1.QL;     // (-.707, -.707)
    b[5] = Rr.QL & Rrp.QL;        // (+.707, -.707)
    b[7] = Rr.QR & Rrp.QR;        // (+.707, +.707)

    unsigned s0, s1, s2, s3;
    sum8(b, s0, s1, s2, s3);
    unsigned ok_s = ~(s3 | (s2 & (s1 | s0)));     // sum < 5

    unsigned ch[8];
#pragma unroll
    for (int k = 0; k < 8; k++) ch[k] = b[k] ^ b[(k + 7) & 7];
    unsigned c0, c1, c2, c3;
    sum8(ch, c0, c1, c2, c3);
    unsigned ok_ch = ~(c2 | c3);                  // changes <= 2 (changes is even)

    g_fbits[gid] = Rr.C & ok_s & ok_ch;           // center must be 1
}

// ---------------- 3) ordered compaction from flag bitmask ------------------------
__global__ void __launch_bounds__(1024) select_kernel() {
    const int img = blockIdx.x;
    __shared__ int s_wtot[32];
    __shared__ int s_woff[32];
    const int tid = threadIdx.x, lane = tid & 31, wrp = tid >> 5;

    g_pts[img][tid] = make_float2(0.0f, 0.0f);    // zero-pad
    g_pti[img][tid] = 0u;

    const unsigned* __restrict__ F = g_fbits + img * 8192;
    unsigned wv[8];
    int cnt = 0;
    const int w0 = tid * 8;
#pragma unroll
    for (int i = 0; i < 8; i++) { wv[i] = __ldg(F + w0 + i); cnt += __popc(wv[i]); }

    // block-wide exclusive prefix
    int incl = cnt;
#pragma unroll
    for (int d = 1; d < 32; d <<= 1) {
        int n = __shfl_up_sync(0xffffffffu, incl, d);
        if (lane >= d) incl += n;
    }
    if (lane == 31) s_wtot[wrp] = incl;
    __syncthreads();
    if (wrp == 0) {
        int t = s_wtot[lane];
        int ti = t;
#pragma unroll
        for (int d = 1; d < 32; d <<= 1) {
            int n = __shfl_up_sync(0xffffffffu, ti, d);
            if (lane >= d) ti += n;
        }
        s_woff[lane] = ti - t;
    }
    __syncthreads();
    int rank = s_woff[wrp] + (incl - cnt);

    if (rank < KP && cnt > 0) {
#pragma unroll
        for (int i = 0; i < 8; i++) {
            unsigned m = wv[i];
            int pbase = (w0 + i) << 5;
            while (m && rank < KP) {
                int b = __ffs(m) - 1;
                m &= m - 1;
                int pp = pbase + b;
                int rr = pp >> 9, cc = pp & 511;
                g_pts[img][rank] = make_float2((float)rr, (float)cc);
                g_pti[img][rank] = ((unsigned)rr << 16) | (unsigned)cc;
                rank++;
            }
            if (rank >= KP) break;
        }
    }
}

// ---------------- 4) Prim's MST: R9 structure, skip == (wm >= THR) ---------------
// Coords scaled x32, packed in smem (v<<5: no field carry). key = dx^2+dy^2+idx
// == 1024*d2 + idx exactly: same ordering and ties as the reference float-sqrt
// argmin. Real keys <= 5.348e8 < 2^29. Retirement MERGED into the update: the
// owner sets px=SENTX and forces key = cand (sentinel-distance in [8.79e8,
// 2.39e9] -- above every real key, below 2^32), so retired nodes never win.
// Warp-retired test: all lanes' lmin >= 2^29 <=> warp-min wm >= 2^29, so the
// redux result doubles as the skip predicate -- no VOTE needed.
__global__ void __launch_bounds__(T_MST) mst_kernel() {
    const int img = blockIdx.x;
    __shared__ unsigned s_xy[KP];
    __shared__ __align__(16) unsigned s_red[2][8];

    const int tid = threadIdx.x;
    const int lane = tid & 31;
    const int wrp = tid >> 5;

    for (int i = tid; i < KP; i += T_MST) s_xy[i] = g_pti[img][i] << 5;  // scaled packed
    __syncthreads();

    unsigned px[NPT], py[NPT], key[NPT];
    int src[NPT];
    const int base = tid * NPT;
    {
        const unsigned xy0 = s_xy[0];
        const unsigned jx = xy0 >> 16, jy = xy0 & 0xffffu;
#pragma unroll
        for (int q = 0; q < NPT; q++) {
            unsigned v = s_xy[base + q];
            px[q] = v >> 16; py[q] = v & 0xffffu;
            unsigned dx = px[q] - jx, dy = py[q] - jy;
            key[q] = dx * dx + dy * dy + (unsigned)(base + q);
            src[q] = 0;
        }
    }
    if (tid == 0) { key[0] = UMAXV; px[0] = SENTX; }

    unsigned lmin = UMAXV;
#pragma unroll
    for (int q = 0; q < NPT; q++) lmin = min(lmin, key[q]);
    unsigned wm = __reduce_min_sync(0xffffffffu, lmin);
    bool skip = (wm >= SKIPTHR);                  // warp fully retired
    if (lane == 0) s_red[0][wrp] = wm;
    __syncthreads();
    uint4 A = *(const uint4*)&s_red[0][0];
    uint4 B = *(const uint4*)&s_red[0][4];
    unsigned gm = min(min(min(A.x, A.y), min(A.z, A.w)),
                      min(min(B.x, B.y), min(B.z, B.w)));
    int j = (int)(gm & 1023u);
    unsigned jxy = s_xy[j];                       // pipelined fetch

    int2* __restrict__ ep = g_edges[img];
#pragma unroll 1
    for (int step = 0; step < KP - 1; step++) {
        if (!skip) {                              // from previous redux result
            const int t = j - base;               // owner iff t in [0, NPT)
            // extract src[j&3] from PRE-update values via SEL tree
            int sA = (t == 1) ? src[1] : src[0];
            int sB = (t == 3) ? src[3] : src[2];
            int srcj = (t >= 2) ? sB : sA;

            const unsigned jx = jxy >> 16, jy = jxy & 0xffffu;
            lmin = UMAXV;
#pragma unroll
            for (int q = 0; q < NPT; q++) {
                bool own = (t == q);
                px[q] = own ? SENTX : px[q];      // sentinel coordinate
                unsigned dx = px[q] - jx, dy = py[q] - jy;
                unsigned cand = dx * dx + dy * dy + (unsigned)(base + q);
                // merged retire: owner unconditionally takes cand (>= SKIPTHR)
                bool upd = own | (cand < key[q]); // strict <, keeps old src on tie
                key[q] = upd ? cand : key[q];
                src[q] = upd ? j : src[q];
                lmin = min(lmin, key[q]);
            }
            if ((unsigned)t < (unsigned)NPT)      // fire-and-forget, off the chain
                ep[step] = make_int2(srcj, j);
        }
        wm = __reduce_min_sync(0xffffffffu, lmin);
        skip = (wm >= SKIPTHR);                   // doubles as next-iter skip
        const int par = (step + 1) & 1;           // double buffer: 1 barrier/iter
        if (lane == 0) s_red[par][wrp] = wm;
        __syncthreads();
        A = *(const uint4*)&s_red[par][0];
        B = *(const uint4*)&s_red[par][4];
        gm = min(min(min(A.x, A.y), min(A.z, A.w)),
                 min(min(B.x, B.y), min(B.z, B.w)));
        j = (int)(gm & 1023u);
        jxy = s_xy[j];                            // prefetch for next iteration
    }
}

// ---------------- 5) per-(sample,tree) loss + fused final ------------------------
__device__ __forceinline__ float pdist2(float2 a, float2 b) {
    float dx = a.x - b.x, dy = a.y - b.y;
    return sqrtf(dx * dx + dy * dy);   // exact: integer d2 < 2^24
}

__global__ void __launch_bounds__(256) loss_kernel(float* __restrict__ out) {
    const int blk = blockIdx.x;        // 16 blocks: (sample s, tree t)
    const int s = blk >> 1;
    const int t = blk & 1;             // 0: pred-tree edges, 1: mask-tree edges
    const int tid = threadIdx.x;

    __shared__ float2 sPp[KP], sPm[KP];
    __shared__ float red[256];
    // coalesced staging of both point sets (16 KB)
    for (int i = tid; i < KP; i += 256) {
        sPp[i] = g_pts[2 * s][i];
        sPm[i] = g_pts[2 * s + 1][i];
    }
    __syncthreads();

    const int2* __restrict__ E = g_edges[2 * s + t];
    float acc = 0.0f;
    for (int e = tid; e < KP - 1; e += 256) {
        int2 ee = E[e];
        float d = pdist2(sPp[ee.x], sPp[ee.y]) - pdist2(sPm[ee.x], sPm[ee.y]);
        acc += d * d;
    }
    red[tid] = acc;
    __syncthreads();
#pragma unroll
    for (int w = 128; w; w >>= 1) {
        if (tid < w) red[tid] += red[tid + w];
        __syncthreads();
    }
    if (tid == 0) {
        g_part[blk] = sqrtf(red[0]);
        __threadfence();
        unsigned done = atomicAdd(&g_cnt, 1u);
        if (done == NIMG - 1) {                   // last block: fused final
            float tt = 0.0f;
#pragma unroll
            for (int i = 0; i < NIMG; i++) tt += g_part[i];
            out[0] = 0.1f * tt / 8.0f;
        }
    }
}

// ---------------- launch ----------------
extern "C" void kernel_launch(void* const* d_in, const int* in_sizes, int n_in,
                              void* d_out, int out_size) {
    const float* model_output = (const float*)d_in[1];
    const float* labels       = (const float*)d_in[2];
    float* out = (float*)d_out;

    binarize_kernel<<<(NS * HW) / 256, 256>>>(model_output, labels);
    lbp_bits_kernel<<<(NIMG * 8192) / 256, 256>>>();
    select_kernel<<<NIMG, 1024>>>();
    mst_kernel<<<NIMG, T_MST>>>();
    loss_kernel<<<NIMG, 256>>>(out);
}